// round 13
// baseline (speedup 1.0000x reference)
#include <cuda_runtime.h>
#include <cuda_bf16.h>
#include <cuda_fp16.h>
#include <math.h>

#define Bc 2
#define NH 6
#define HD 32
#define Dz 16
#define Hy 32
#define Wx 32
#define NS (Dz*Hy*Wx)      // 16384
#define CH 192
#define SCALE 0.17677669529663687f
#define AW 4               // warps per attention block

// Output regions (tuple concat): out, offs, offset_mag, branch_energy, guide
#define O_OUT   0
#define O_OFFS  6291456     // 2*192*16384
#define O_MAG   6881280     // + 2*6*16384*3
#define O_EN    6881292
#define O_GUIDE 6881296

// Scratch (device globals; allocation-free)
__device__ float   g_qT[Bc*NH*NS*HD];      // [bh][s][hd]
__device__ __half2 g_kvh[Bc*NH*NS*HD];     // [bh][s][hd] -> (k, v) fp16
__device__ float   g_tT[Bc*NH*NS*HD];
__device__ float   g_lepeT[Bc*NH*NS*HD];
__device__ float   g_attnC[Bc*CH*NS];      // [b][c][s]  (attn + lepe)
__device__ float   g_offs[Bc*NH*NS*3];
__device__ float   g_mag[Bc*NH];
__device__ float   g_energy[Bc*2];

__device__ __forceinline__ float warpSum(float v) {
#pragma unroll
    for (int o = 16; o; o >>= 1) v += __shfl_xor_sync(0xffffffffu, v, o);
    return v;
}

__global__ void k_zero() {
    int t = threadIdx.x;
    if (t < Bc*NH) g_mag[t] = 0.f;
    if (t < Bc*2)  g_energy[t] = 0.f;
}

// ================= GEMM: q conv  X[b,c,s] x qw -> g_qT [bh][s][hd]  (R8 64x64) ==========
__global__ __launch_bounds__(256) void k_gemm_q(const float* __restrict__ X,
                                                const float* __restrict__ W,
                                                const float* __restrict__ bias)
{
    const int b  = blockIdx.z;
    const int o0 = blockIdx.y * 64;
    const int s0 = blockIdx.x * 64;
    const int tid = threadIdx.x;
    const int tx = tid & 15, ty = tid >> 4;

    __shared__ __align__(16) float sW[16][68];
    __shared__ __align__(16) float sX[16][68];
    __shared__ float sC[64][65];

    float acc[4][4] = {};
    const float* Xb = X + (size_t)b * CH * NS;

    for (int kk = 0; kk < CH; kk += 16) {
        {
            int r = tid >> 2, cq = (tid & 3) * 4;
            float4 w4 = *(const float4*)&W[(o0 + r) * CH + kk + cq];
            sW[cq + 0][r] = w4.x; sW[cq + 1][r] = w4.y;
            sW[cq + 2][r] = w4.z; sW[cq + 3][r] = w4.w;
        }
        {
            int r = tid >> 4, cq = (tid & 15) * 4;
            *(float4*)&sX[r][cq] = *(const float4*)&Xb[(size_t)(kk + r) * NS + s0 + cq];
        }
        __syncthreads();
#pragma unroll
        for (int k = 0; k < 16; k++) {
            float4 av = *(const float4*)&sW[k][ty * 4];
            float4 bv = *(const float4*)&sX[k][tx * 4];
            acc[0][0] += av.x*bv.x; acc[0][1] += av.x*bv.y; acc[0][2] += av.x*bv.z; acc[0][3] += av.x*bv.w;
            acc[1][0] += av.y*bv.x; acc[1][1] += av.y*bv.y; acc[1][2] += av.y*bv.z; acc[1][3] += av.y*bv.w;
            acc[2][0] += av.z*bv.x; acc[2][1] += av.z*bv.y; acc[2][2] += av.z*bv.z; acc[2][3] += av.z*bv.w;
            acc[3][0] += av.w*bv.x; acc[3][1] += av.w*bv.y; acc[3][2] += av.w*bv.z; acc[3][3] += av.w*bv.w;
        }
        __syncthreads();
    }
#pragma unroll
    for (int i = 0; i < 4; i++) {
        float bv = bias[o0 + ty * 4 + i];
#pragma unroll
        for (int j = 0; j < 4; j++) sC[ty * 4 + i][tx * 4 + j] = acc[i][j] + bv;
    }
    __syncthreads();
#pragma unroll
    for (int it = 0; it < 16; ++it) {
        int idx = tid + it * 256;
        int sl = idx >> 6, ol = idx & 63;
        int o = o0 + ol;
        g_qT[(((size_t)b * NH + (o >> 5)) * NS + (s0 + sl)) * HD + (o & 31)] = sC[ol][sl];
    }
}

// ================= GEMM: fused k & v conv -> g_kvh half2  (R8 64x64) =================
__global__ __launch_bounds__(256) void k_gemm_kv(const float* __restrict__ X,
                                                 const float* __restrict__ Wk, const float* __restrict__ bk,
                                                 const float* __restrict__ Wv, const float* __restrict__ bv_)
{
    const int b  = blockIdx.z;
    const int o0 = blockIdx.y * 64;
    const int s0 = blockIdx.x * 64;
    const int tid = threadIdx.x;
    const int tx = tid & 15, ty = tid >> 4;

    __shared__ __align__(16) float sWk[16][68];
    __shared__ __align__(16) float sWv[16][68];
    __shared__ __align__(16) float sX[16][68];
    __shared__ __half2 sC2[64][65];

    float ak[4][4] = {}, av_[4][4] = {};
    const float* Xb = X + (size_t)b * CH * NS;

    for (int kk = 0; kk < CH; kk += 16) {
        {
            int r = tid >> 2, cq = (tid & 3) * 4;
            float4 w4 = *(const float4*)&Wk[(o0 + r) * CH + kk + cq];
            sWk[cq + 0][r] = w4.x; sWk[cq + 1][r] = w4.y; sWk[cq + 2][r] = w4.z; sWk[cq + 3][r] = w4.w;
            float4 v4 = *(const float4*)&Wv[(o0 + r) * CH + kk + cq];
            sWv[cq + 0][r] = v4.x; sWv[cq + 1][r] = v4.y; sWv[cq + 2][r] = v4.z; sWv[cq + 3][r] = v4.w;
        }
        {
            int r = tid >> 4, cq = (tid & 15) * 4;
            *(float4*)&sX[r][cq] = *(const float4*)&Xb[(size_t)(kk + r) * NS + s0 + cq];
        }
        __syncthreads();
#pragma unroll
        for (int k = 0; k < 16; k++) {
            float4 wa = *(const float4*)&sWk[k][ty * 4];
            float4 wb = *(const float4*)&sWv[k][ty * 4];
            float4 xv = *(const float4*)&sX[k][tx * 4];
            ak[0][0] += wa.x*xv.x; ak[0][1] += wa.x*xv.y; ak[0][2] += wa.x*xv.z; ak[0][3] += wa.x*xv.w;
            ak[1][0] += wa.y*xv.x; ak[1][1] += wa.y*xv.y; ak[1][2] += wa.y*xv.z; ak[1][3] += wa.y*xv.w;
            ak[2][0] += wa.z*xv.x; ak[2][1] += wa.z*xv.y; ak[2][2] += wa.z*xv.z; ak[2][3] += wa.z*xv.w;
            ak[3][0] += wa.w*xv.x; ak[3][1] += wa.w*xv.y; ak[3][2] += wa.w*xv.z; ak[3][3] += wa.w*xv.w;
            av_[0][0] += wb.x*xv.x; av_[0][1] += wb.x*xv.y; av_[0][2] += wb.x*xv.z; av_[0][3] += wb.x*xv.w;
            av_[1][0] += wb.y*xv.x; av_[1][1] += wb.y*xv.y; av_[1][2] += wb.y*xv.z; av_[1][3] += wb.y*xv.w;
            av_[2][0] += wb.z*xv.x; av_[2][1] += wb.z*xv.y; av_[2][2] += wb.z*xv.z; av_[2][3] += wb.z*xv.w;
            av_[3][0] += wb.w*xv.x; av_[3][1] += wb.w*xv.y; av_[3][2] += wb.w*xv.z; av_[3][3] += wb.w*xv.w;
        }
        __syncthreads();
    }
#pragma unroll
    for (int i = 0; i < 4; i++) {
        int o = o0 + ty * 4 + i;
        float bkk = bk[o], bvv = bv_[o];
#pragma unroll
        for (int j = 0; j < 4; j++)
            sC2[ty * 4 + i][tx * 4 + j] = __floats2half2_rn(ak[i][j] + bkk, av_[i][j] + bvv);
    }
    __syncthreads();
#pragma unroll
    for (int it = 0; it < 16; ++it) {
        int idx = tid + it * 256;
        int sl = idx >> 6, ol = idx & 63;
        int o = o0 + ol;
        g_kvh[(((size_t)b * NH + (o >> 5)) * NS + (s0 + sl)) * HD + (o & 31)] = sC2[ol][sl];
    }
}

// ================= depthwise 3x3x3 on qT -> tT & lepeT (x-register-blocked) =================
__global__ __launch_bounds__(256) void k_dwconv(const float* __restrict__ odw, const float* __restrict__ odb,
                                                const float* __restrict__ rpew, const float* __restrict__ rpeb)
{
    const int bh = blockIdx.y;
    const int h = bh % NH;
    const int lane = threadIdx.x & 31, wid = threadIdx.x >> 5;

    __shared__ float sWt[27][32];
    __shared__ float sWl[27][32];
    for (int idx = threadIdx.x; idx < 27 * 32; idx += 256) {
        int c = idx & 31, tap = idx >> 5;
        sWt[tap][c] = odw[(h * 32 + c) * 27 + tap];
        sWl[tap][c] = rpew[(h * 32 + c) * 27 + tap];
    }
    __syncthreads();

    const float bt = odb[h * 32 + lane];
    const float bl = rpeb[h * 32 + lane];
    const float* base = g_qT + (size_t)bh * NS * HD;

    const int s0 = blockIdx.x * 64 + wid * 8;
    const int z = s0 >> 10, y = (s0 >> 5) & 31, xb = s0 & 31;

    float at[8], al[8];
#pragma unroll
    for (int p = 0; p < 8; p++) { at[p] = bt; al[p] = bl; }

#pragma unroll
    for (int kd = 0; kd < 3; kd++) {
        int zz = z + kd - 1;
        if ((unsigned)zz >= (unsigned)Dz) continue;
#pragma unroll
        for (int kh = 0; kh < 3; kh++) {
            int yy = y + kh - 1;
            if ((unsigned)yy >= (unsigned)Hy) continue;
            const float* rowp = base + (size_t)(zz * 1024 + yy * 32) * 32 + lane;
            float w[10];
#pragma unroll
            for (int i = 0; i < 10; i++) {
                int xx = xb - 1 + i;
                w[i] = ((unsigned)xx < (unsigned)Wx) ? rowp[xx * 32] : 0.f;
            }
            const int t0 = (kd * 3 + kh) * 3;
            const float wt0 = sWt[t0][lane], wt1 = sWt[t0 + 1][lane], wt2 = sWt[t0 + 2][lane];
            const float wl0 = sWl[t0][lane], wl1 = sWl[t0 + 1][lane], wl2 = sWl[t0 + 2][lane];
#pragma unroll
            for (int p = 0; p < 8; p++) {
                at[p] += w[p] * wt0 + w[p + 1] * wt1 + w[p + 2] * wt2;
                al[p] += w[p] * wl0 + w[p + 1] * wl1 + w[p + 2] * wl2;
            }
        }
    }
#pragma unroll
    for (int p = 0; p < 8; p++) {
        size_t oi = ((size_t)bh * NS + s0 + p) * 32 + lane;
        g_tT[oi] = at[p];
        g_lepeT[oi] = al[p];
    }
}

// ================= LN + GELU + offset conv + tanh*scale =================
__global__ void k_offsets(const float* __restrict__ lnw, const float* __restrict__ lnb,
                          const float* __restrict__ opw, const float* __restrict__ opb,
                          float* __restrict__ d_out)
{
    __shared__ float sOp[18 * 192];
    __shared__ float sLn[2][192];
    for (int i = threadIdx.x; i < 18 * 192; i += 256) sOp[i] = opw[i];
    for (int i = threadIdx.x; i < 192; i += 256) { sLn[0][i] = lnw[i]; sLn[1][i] = lnb[i]; }
    __syncthreads();

    const int lane = threadIdx.x & 31, wid = threadIdx.x >> 5;
    const int gid = blockIdx.x * 8 + wid;
    const int b = gid >> 14;
    const int s = gid & (NS - 1);

    float v[6];
#pragma unroll
    for (int h = 0; h < 6; h++) v[h] = g_tT[(((size_t)b * 6 + h) * NS + s) * 32 + lane];

    float sm = 0.f;
#pragma unroll
    for (int h = 0; h < 6; h++) sm += v[h];
    sm = warpSum(sm);
    float mean = sm * (1.f / 192.f);
    float s2 = 0.f;
#pragma unroll
    for (int h = 0; h < 6; h++) { float d = v[h] - mean; s2 += d * d; }
    s2 = warpSum(s2);
    float inv = rsqrtf(s2 * (1.f / 192.f) + 1e-5f);

    float g[6];
#pragma unroll
    for (int h = 0; h < 6; h++) {
        int c = h * 32 + lane;
        float n = (v[h] - mean) * inv * sLn[0][c] + sLn[1][c];
        g[h] = 0.5f * n * (1.f + erff(n * 0.70710678118654752f));
    }

    float p18[18];
#pragma unroll
    for (int o = 0; o < 18; o++) {
        float p = 0.f;
#pragma unroll
        for (int h = 0; h < 6; h++) p += g[h] * sOp[o * 192 + h * 32 + lane];
        p18[o] = p;
    }
#pragma unroll
    for (int o = 16; o; o >>= 1)
#pragma unroll
        for (int j = 0; j < 18; j++) p18[j] += __shfl_xor_sync(0xffffffffu, p18[j], o);

    float mine = 0.f;
#pragma unroll
    for (int j = 0; j < 18; j++) if (lane == j) mine = p18[j];

    float ov = 0.f;
    if (lane < 18) {
        float val = tanhf(mine + opb[lane]);
        int comp = lane % 3;
        float sc = (comp == 2) ? (2.f / 15.f) : (2.f / 31.f);
        ov = val * sc;
        int h = lane / 3;
        size_t oi = (((size_t)b * 6 + h) * NS + s) * 3 + comp;
        g_offs[oi] = ov;
        d_out[O_OFFS + oi] = ov;
    }
    float ox = __shfl_sync(0xffffffffu, ov, (lane < 6) ? 3 * lane : 0);
    float oy = __shfl_sync(0xffffffffu, ov, (lane < 6) ? 3 * lane + 1 : 0);
    float oz = __shfl_sync(0xffffffffu, ov, (lane < 6) ? 3 * lane + 2 : 0);
    if (lane < 6) atomicAdd(&g_mag[b * 6 + lane], sqrtf(ox * ox + oy * oy + oz * oz));
}

// ================= attention epilogue (AW warps, 128 threads) =================
__device__ __forceinline__ void attn_epilogue(float res, int b, int h, int bi,
                                              int lane, int wid, int s0b, size_t qi)
{
    float outv = res + g_lepeT[qi];
    __shared__ float sT[AW][33];
    __shared__ float sE[AW];
    sT[wid][lane] = outv;
    float e = warpSum(fabsf(res));
    if (lane == 0) sE[wid] = e;
    __syncthreads();
    int ch = threadIdx.x >> 2, si = threadIdx.x & 3;
    g_attnC[((size_t)b * CH + h * 32 + ch) * NS + s0b + si] = sT[si][ch];
    if (threadIdx.x == 0) {
        float t = 0.f;
#pragma unroll
        for (int i = 0; i < AW; i++) t += sE[i];
        atomicAdd(&g_energy[b * 2 + bi], t);
    }
}

// xy-lerped plane, one component (SEL 0=k, 1=v); 4x4 lattice (overlapping pairs)
template<int SEL>
__device__ __forceinline__ void plane4c(const __half2* __restrict__ kv, int zoff,
                                        const int* LYo, const int* LXo,
                                        float wx, float wy, float* out9)
{
    float Ap[3];
#pragma unroll
    for (int ty = 0; ty < 4; ty++) {
        float p0, p1, p2, p3;
        {
            float2 f0 = __half22float2(kv[zoff + LYo[ty] + LXo[0]]);
            float2 f1 = __half22float2(kv[zoff + LYo[ty] + LXo[1]]);
            float2 f2 = __half22float2(kv[zoff + LYo[ty] + LXo[2]]);
            float2 f3 = __half22float2(kv[zoff + LYo[ty] + LXo[3]]);
            p0 = SEL ? f0.y : f0.x; p1 = SEL ? f1.y : f1.x;
            p2 = SEL ? f2.y : f2.x; p3 = SEL ? f3.y : f3.x;
        }
        float A[3];
        A[0] = p0 + wx * (p1 - p0);
        A[1] = p1 + wx * (p2 - p1);
        A[2] = p2 + wx * (p3 - p2);
        if (ty > 0) {
#pragma unroll
            for (int jx = 0; jx < 3; jx++)
                out9[(ty - 1) * 3 + jx] = Ap[jx] + wy * (A[jx] - Ap[jx]);
        }
#pragma unroll
        for (int jx = 0; jx < 3; jx++) Ap[jx] = A[jx];
    }
}

// xy-lerped plane, one component; 6x6 lattice (disjoint pairs)
template<int SEL>
__device__ __forceinline__ void plane6c(const __half2* __restrict__ kv, int zoff,
                                        const int* LYo, const int* LXo,
                                        float wx, float wy, float* out9)
{
#pragma unroll
    for (int u = 0; u < 3; u++) {
#pragma unroll
        for (int jx = 0; jx < 3; jx++) {
            float2 fa0 = __half22float2(kv[zoff + LYo[2 * u] + LXo[2 * jx]]);
            float2 fc0 = __half22float2(kv[zoff + LYo[2 * u] + LXo[2 * jx + 1]]);
            float2 fa1 = __half22float2(kv[zoff + LYo[2 * u + 1] + LXo[2 * jx]]);
            float2 fc1 = __half22float2(kv[zoff + LYo[2 * u + 1] + LXo[2 * jx + 1]]);
            float a0 = SEL ? fa0.y : fa0.x, c0 = SEL ? fc0.y : fc0.x;
            float a1 = SEL ? fa1.y : fa1.x, c1 = SEL ? fc1.y : fc1.x;
            float A0 = a0 + wx * (c0 - a0);
            float A1 = a1 + wx * (c1 - a1);
            out9[u * 3 + jx] = A0 + wy * (A1 - A0);
        }
    }
}

// softmax weights from reduced scores; returns l, fills p[27] (unnormalized)
__device__ __forceinline__ float softmax_w(float* sc, const float* bias)
{
#pragma unroll
    for (int o = 16; o; o >>= 1)
#pragma unroll
        for (int j = 0; j < 27; j++) sc[j] += __shfl_xor_sync(0xffffffffu, sc[j], o);
    float m = -1e30f;
#pragma unroll
    for (int j = 0; j < 27; j++) { sc[j] = sc[j] * SCALE + bias[j]; m = fmaxf(m, sc[j]); }
    float l = 0.f;
#pragma unroll
    for (int j = 0; j < 27; j++) { sc[j] = __expf(sc[j] - m); l += sc[j]; }
    return l;
}

// ================= attention branch 0 (dil=1): two-pass, 4x4x4 lattice =================
__global__ __launch_bounds__(128, 5) void k_attn1(const float* __restrict__ bias0)
{
    const int bhh = blockIdx.y;
    const int b = bhh / 3, hh = bhh % 3;
    const int h = hh;
    const int bh = b * NH + h;
    const float* bias = bias0 + hh * 27;

    const int lane = threadIdx.x & 31, wid = threadIdx.x >> 5;
    const int s0b = blockIdx.x * AW;
    const int s = s0b + wid;
    const int z = s >> 10, y = (s >> 5) & 31, x = s & 31;

    const size_t qi = ((size_t)bh * NS + s) * 32 + lane;
    const float q = g_qT[qi];
    const float* ob = g_offs + ((size_t)bh * NS + s) * 3;
    const float bx = (float)x + ob[0] * 15.5f;
    const float by = (float)y + ob[1] * 15.5f;
    const float bz = (float)z + ob[2] * 7.5f;

    const __half2* __restrict__ kv = g_kvh + (size_t)bh * NS * HD;

    float fx = floorf(bx), fy = floorf(by), fz = floorf(bz);
    int X0 = (int)fx, Y0 = (int)fy, Z0 = (int)fz;
    float wx = bx - fx, wy = by - fy, wz = bz - fz;
    float uz = 1.f - wz;

    int LXo[4], LYo[4], LZo[4];
#pragma unroll
    for (int t = 0; t < 4; t++) {
        LXo[t] = min(max(X0 - 1 + t, 0), 31) * 32 + lane;
        LYo[t] = min(max(Y0 - 1 + t, 0), 31) * 1024;
        LZo[t] = min(max(Z0 - 1 + t, 0), 15) * 32768;
    }

    // -------- pass 1: k scores --------
    float sc[27];
#pragma unroll
    for (int j = 0; j < 27; j++) sc[j] = 0.f;
#pragma unroll
    for (int tz = 0; tz < 4; tz++) {
        float Bk[9];
        plane4c<0>(kv, LZo[tz], LYo, LXo, wx, wy, Bk);
        if (tz < 3) {
#pragma unroll
            for (int r = 0; r < 9; r++) sc[tz * 9 + r] += uz * Bk[r];
        }
        if (tz > 0) {
#pragma unroll
            for (int r = 0; r < 9; r++) sc[(tz - 1) * 9 + r] += wz * Bk[r];
        }
    }
#pragma unroll
    for (int j = 0; j < 27; j++) sc[j] *= q;
    float l = softmax_w(sc, bias);   // sc now holds p[27]

    // -------- pass 2: weighted v accumulation --------
    float acc = 0.f;
#pragma unroll
    for (int tz = 0; tz < 4; tz++) {
        float Bv[9];
        plane4c<1>(kv, LZo[tz], LYo, LXo, wx, wy, Bv);
#pragma unroll
        for (int r = 0; r < 9; r++) {
            float c = 0.f;
            if (tz < 3) c += uz * sc[tz * 9 + r];
            if (tz > 0) c += wz * sc[(tz - 1) * 9 + r];
            acc += c * Bv[r];
        }
    }
    attn_epilogue(acc / l, b, h, 0, lane, wid, s0b, qi);
}

// ============ attention branch 1 (dil=2): two-pass, 6x6x6 lattice ============
__global__ __launch_bounds__(128, 5) void k_attn2(const float* __restrict__ bias1)
{
    const int bhh = blockIdx.y;
    const int b = bhh / 3, hh = bhh % 3;
    const int h = hh + 3;
    const int bh = b * NH + h;
    const float* bias = bias1 + hh * 27;

    const int lane = threadIdx.x & 31, wid = threadIdx.x >> 5;
    const int s0b = blockIdx.x * AW;
    const int s = s0b + wid;
    const int z = s >> 10, y = (s >> 5) & 31, x = s & 31;

    const size_t qi = ((size_t)bh * NS + s) * 32 + lane;
    const float q = g_qT[qi];
    const float* ob = g_offs + ((size_t)bh * NS + s) * 3;
    const float bx = (float)x + ob[0] * 15.5f;
    const float by = (float)y + ob[1] * 15.5f;
    const float bz = (float)z + ob[2] * 7.5f;

    const __half2* __restrict__ kv = g_kvh + (size_t)bh * NS * HD;

    float fx = floorf(bx), fy = floorf(by), fz = floorf(bz);
    int X0 = (int)fx, Y0 = (int)fy, Z0 = (int)fz;
    float wx = bx - fx, wy = by - fy, wz = bz - fz;
    float uz = 1.f - wz;

    int LXo[6], LYo[6], LZo[6];
#pragma unroll
    for (int t = 0; t < 6; t++) {
        LXo[t] = min(max(X0 - 2 + t, 0), 31) * 32 + lane;
        LYo[t] = min(max(Y0 - 2 + t, 0), 31) * 1024;
        LZo[t] = min(max(Z0 - 2 + t, 0), 15) * 32768;
    }

    // -------- pass 1: k scores --------
    float sc[27];
#pragma unroll
    for (int jz = 0; jz < 3; jz++) {
        float Bk[9];
        plane6c<0>(kv, LZo[2 * jz], LYo, LXo, wx, wy, Bk);
#pragma unroll
        for (int r = 0; r < 9; r++) sc[jz * 9 + r] = uz * Bk[r];
        plane6c<0>(kv, LZo[2 * jz + 1], LYo, LXo, wx, wy, Bk);
#pragma unroll
        for (int r = 0; r < 9; r++) sc[jz * 9 + r] += wz * Bk[r];
    }
#pragma unroll
    for (int j = 0; j < 27; j++) sc[j] *= q;
    float l = softmax_w(sc, bias);   // sc now holds p[27]

    // -------- pass 2: weighted v accumulation --------
    float acc = 0.f;
#pragma unroll
    for (int jz = 0; jz < 3; jz++) {
        float Bv[9];
        plane6c<1>(kv, LZo[2 * jz], LYo, LXo, wx, wy, Bv);
#pragma unroll
        for (int r = 0; r < 9; r++) acc += uz * sc[jz * 9 + r] * Bv[r];
        plane6c<1>(kv, LZo[2 * jz + 1], LYo, LXo, wx, wy, Bv);
#pragma unroll
        for (int r = 0; r < 9; r++) acc += wz * sc[jz * 9 + r] * Bv[r];
    }
    attn_epilogue(acc / l, b, h, 1, lane, wid, s0b, qi);
}

// ================= final conv: g_attnC [b,c,s] x pw -> out [b,c,s]  (R8 64x64) ==========
__global__ __launch_bounds__(256) void k_gemm_final(const float* __restrict__ W,
                                                    const float* __restrict__ bias,
                                                    float* __restrict__ out)
{
    const int b  = blockIdx.z;
    const int o0 = blockIdx.y * 64;
    const int s0 = blockIdx.x * 64;
    const int tid = threadIdx.x;
    const int tx = tid & 15, ty = tid >> 4;

    __shared__ __align__(16) float sW[16][68];
    __shared__ __align__(16) float sX[16][68];

    float acc[4][4] = {};
    const float* Xb = g_attnC + (size_t)b * CH * NS;

    for (int kk = 0; kk < CH; kk += 16) {
        {
            int r = tid >> 2, cq = (tid & 3) * 4;
            float4 w4 = *(const float4*)&W[(o0 + r) * CH + kk + cq];
            sW[cq + 0][r] = w4.x; sW[cq + 1][r] = w4.y;
            sW[cq + 2][r] = w4.z; sW[cq + 3][r] = w4.w;
        }
        {
            int r = tid >> 4, cq = (tid & 15) * 4;
            *(float4*)&sX[r][cq] = *(const float4*)&Xb[(size_t)(kk + r) * NS + s0 + cq];
        }
        __syncthreads();
#pragma unroll
        for (int k = 0; k < 16; k++) {
            float4 av = *(const float4*)&sW[k][ty * 4];
            float4 bv = *(const float4*)&sX[k][tx * 4];
            acc[0][0] += av.x*bv.x; acc[0][1] += av.x*bv.y; acc[0][2] += av.x*bv.z; acc[0][3] += av.x*bv.w;
            acc[1][0] += av.y*bv.x; acc[1][1] += av.y*bv.y; acc[1][2] += av.y*bv.z; acc[1][3] += av.y*bv.w;
            acc[2][0] += av.z*bv.x; acc[2][1] += av.z*bv.y; acc[2][2] += av.z*bv.z; acc[2][3] += av.z*bv.w;
            acc[3][0] += av.w*bv.x; acc[3][1] += av.w*bv.y; acc[3][2] += av.w*bv.z; acc[3][3] += av.w*bv.w;
        }
        __syncthreads();
    }
#pragma unroll
    for (int i = 0; i < 4; i++) {
        int o = o0 + ty * 4 + i;
        float bv = bias[o];
        float4 r = make_float4(acc[i][0] + bv, acc[i][1] + bv, acc[i][2] + bv, acc[i][3] + bv);
        *(float4*)&out[O_OUT + ((size_t)b * CH + o) * NS + s0 + tx * 4] = r;
    }
}

__global__ void k_finalize(float* __restrict__ out)
{
    int t = threadIdx.x;
    const float inv_sp = 1.f / (float)NS;
    const float inv_en = 1.f / (3.f * 32.f * (float)NS);
    if (t < 12) out[O_MAG + t] = g_mag[t] * inv_sp;
    if (t < 4)  out[O_EN + t] = g_energy[t] * inv_en;
    if (t < 16) {
        int b = t >> 3, j = t & 7;
        out[O_GUIDE + t] = (j < 6) ? g_mag[b * 6 + j] * inv_sp
                                   : g_energy[b * 2 + (j - 6)] * inv_en;
    }
}

extern "C" void kernel_launch(void* const* d_in, const int* in_sizes, int n_in,
                              void* d_out, int out_size)
{
    const float* x    = (const float*)d_in[0];
    const float* qw   = (const float*)d_in[1];
    const float* qb   = (const float*)d_in[2];
    const float* kw   = (const float*)d_in[3];
    const float* kbi  = (const float*)d_in[4];
    const float* vw   = (const float*)d_in[5];
    const float* vbi  = (const float*)d_in[6];
    const float* pw   = (const float*)d_in[7];
    const float* pb   = (const float*)d_in[8];
    const float* odw  = (const float*)d_in[9];
    const float* odb  = (const float*)d_in[10];
    const float* lnw  = (const float*)d_in[11];
    const float* lnb  = (const float*)d_in[12];
    const float* opw  = (const float*)d_in[13];
    const float* opb  = (const float*)d_in[14];
    const float* rpew = (const float*)d_in[15];
    const float* rpeb = (const float*)d_in[16];
    const float* b0   = (const float*)d_in[17];
    const float* b1   = (const float*)d_in[18];
    float* out = (float*)d_out;

    k_zero<<<1, 32>>>();

    dim3 gG(NS / 64, CH / 64, Bc);
    k_gemm_q<<<gG, 256>>>(x, qw, qb);
    k_gemm_kv<<<gG, 256>>>(x, kw, kbi, vw, vbi);

    k_dwconv<<<dim3(NS / 64, Bc * NH), 256>>>(odw, odb, rpew, rpeb);
    k_offsets<<<dim3(Bc * NS / 8), 256>>>(lnw, lnb, opw, opb, out);

    k_attn1<<<dim3(NS / AW, Bc * 3), 128>>>(b0);
    k_attn2<<<dim3(NS / AW, Bc * 3), 128>>>(b1);

    k_gemm_final<<<gG, 256>>>(pw, pb, out);
    k_finalize<<<1, 32>>>(out);
}

// round 14
// speedup vs baseline: 1.3480x; 1.3480x over previous
#include <cuda_runtime.h>
#include <cuda_bf16.h>
#include <cuda_fp16.h>
#include <math.h>

#define Bc 2
#define NH 6
#define HD 32
#define Dz 16
#define Hy 32
#define Wx 32
#define NS (Dz*Hy*Wx)      // 16384
#define CH 192
#define SCALE 0.17677669529663687f

// Output regions (tuple concat): out, offs, offset_mag, branch_energy, guide
#define O_OUT   0
#define O_OFFS  6291456     // 2*192*16384
#define O_MAG   6881280     // + 2*6*16384*3
#define O_EN    6881292
#define O_GUIDE 6881296

// Scratch (device globals; allocation-free)
__device__ float   g_qT[Bc*NH*NS*HD];      // [bh][s][hd]
__device__ __half2 g_kvh[Bc*NH*NS*HD];     // [bh][s][hd] -> (k, v) fp16
__device__ float   g_tT[Bc*NH*NS*HD];
__device__ float   g_lepeT[Bc*NH*NS*HD];
__device__ float   g_attnC[Bc*CH*NS];      // [b][c][s]  (attn + lepe)
__device__ float   g_offs[Bc*NH*NS*3];
__device__ float   g_mag[Bc*NH];
__device__ float   g_energy[Bc*2];

__device__ __forceinline__ float warpSum(float v) {
#pragma unroll
    for (int o = 16; o; o >>= 1) v += __shfl_xor_sync(0xffffffffu, v, o);
    return v;
}

__global__ void k_zero() {
    int t = threadIdx.x;
    if (t < Bc*NH) g_mag[t] = 0.f;
    if (t < Bc*2)  g_energy[t] = 0.f;
}

// ========== FUSED GEMM: q, k, v conv in one pass over X (64x64 tiles) ==========
__global__ __launch_bounds__(256) void k_gemm_qkv(const float* __restrict__ X,
                                                  const float* __restrict__ Wq, const float* __restrict__ bq,
                                                  const float* __restrict__ Wk, const float* __restrict__ bk,
                                                  const float* __restrict__ Wv, const float* __restrict__ bv_)
{
    const int b  = blockIdx.z;
    const int o0 = blockIdx.y * 64;
    const int s0 = blockIdx.x * 64;
    const int tid = threadIdx.x;
    const int tx = tid & 15, ty = tid >> 4;

    __shared__ __align__(16) float sWq[16][68];
    __shared__ __align__(16) float sWk[16][68];
    __shared__ __align__(16) float sWv[16][68];
    __shared__ __align__(16) float sX[16][68];
    __shared__ __align__(16) float sC[64][65];     // staging: first q (float), then kv (half2)

    float aq[4][4] = {}, ak[4][4] = {}, av_[4][4] = {};
    const float* Xb = X + (size_t)b * CH * NS;

    for (int kk = 0; kk < CH; kk += 16) {
        {
            int r = tid >> 2, cq = (tid & 3) * 4;
            float4 wq4 = *(const float4*)&Wq[(o0 + r) * CH + kk + cq];
            sWq[cq + 0][r] = wq4.x; sWq[cq + 1][r] = wq4.y; sWq[cq + 2][r] = wq4.z; sWq[cq + 3][r] = wq4.w;
            float4 wk4 = *(const float4*)&Wk[(o0 + r) * CH + kk + cq];
            sWk[cq + 0][r] = wk4.x; sWk[cq + 1][r] = wk4.y; sWk[cq + 2][r] = wk4.z; sWk[cq + 3][r] = wk4.w;
            float4 wv4 = *(const float4*)&Wv[(o0 + r) * CH + kk + cq];
            sWv[cq + 0][r] = wv4.x; sWv[cq + 1][r] = wv4.y; sWv[cq + 2][r] = wv4.z; sWv[cq + 3][r] = wv4.w;
        }
        {
            int r = tid >> 4, cq = (tid & 15) * 4;
            *(float4*)&sX[r][cq] = *(const float4*)&Xb[(size_t)(kk + r) * NS + s0 + cq];
        }
        __syncthreads();
#pragma unroll
        for (int k = 0; k < 16; k++) {
            float4 wq = *(const float4*)&sWq[k][ty * 4];
            float4 wk = *(const float4*)&sWk[k][ty * 4];
            float4 wv = *(const float4*)&sWv[k][ty * 4];
            float4 xv = *(const float4*)&sX[k][tx * 4];
            float wqv[4] = {wq.x, wq.y, wq.z, wq.w};
            float wkv[4] = {wk.x, wk.y, wk.z, wk.w};
            float wvv[4] = {wv.x, wv.y, wv.z, wv.w};
            float xvv[4] = {xv.x, xv.y, xv.z, xv.w};
#pragma unroll
            for (int i = 0; i < 4; i++)
#pragma unroll
                for (int j = 0; j < 4; j++) {
                    aq[i][j]  += wqv[i] * xvv[j];
                    ak[i][j]  += wkv[i] * xvv[j];
                    av_[i][j] += wvv[i] * xvv[j];
                }
        }
        __syncthreads();
    }

    // ---- stage + write q ----
#pragma unroll
    for (int i = 0; i < 4; i++) {
        float bv = bq[o0 + ty * 4 + i];
#pragma unroll
        for (int j = 0; j < 4; j++) sC[ty * 4 + i][tx * 4 + j] = aq[i][j] + bv;
    }
    __syncthreads();
#pragma unroll
    for (int it = 0; it < 16; ++it) {
        int idx = tid + it * 256;
        int sl = idx >> 6, ol = idx & 63;
        int o = o0 + ol;
        g_qT[(((size_t)b * NH + (o >> 5)) * NS + (s0 + sl)) * HD + (o & 31)] = sC[ol][sl];
    }
    __syncthreads();

    // ---- stage + write kv (reuse sC as half2) ----
    __half2 (*sC2)[65] = reinterpret_cast<__half2(*)[65]>(sC);
#pragma unroll
    for (int i = 0; i < 4; i++) {
        int o = o0 + ty * 4 + i;
        float bkk = bk[o], bvv = bv_[o];
#pragma unroll
        for (int j = 0; j < 4; j++)
            sC2[ty * 4 + i][tx * 4 + j] = __floats2half2_rn(ak[i][j] + bkk, av_[i][j] + bvv);
    }
    __syncthreads();
#pragma unroll
    for (int it = 0; it < 16; ++it) {
        int idx = tid + it * 256;
        int sl = idx >> 6, ol = idx & 63;
        int o = o0 + ol;
        g_kvh[(((size_t)b * NH + (o >> 5)) * NS + (s0 + sl)) * HD + (o & 31)] = sC2[ol][sl];
    }
}

// ================= depthwise 3x3x3 on qT -> tT & lepeT (x-register-blocked) =================
__global__ __launch_bounds__(256) void k_dwconv(const float* __restrict__ odw, const float* __restrict__ odb,
                                                const float* __restrict__ rpew, const float* __restrict__ rpeb)
{
    const int bh = blockIdx.y;
    const int h = bh % NH;
    const int lane = threadIdx.x & 31, wid = threadIdx.x >> 5;

    __shared__ float sWt[27][32];
    __shared__ float sWl[27][32];
    for (int idx = threadIdx.x; idx < 27 * 32; idx += 256) {
        int c = idx & 31, tap = idx >> 5;
        sWt[tap][c] = odw[(h * 32 + c) * 27 + tap];
        sWl[tap][c] = rpew[(h * 32 + c) * 27 + tap];
    }
    __syncthreads();

    const float bt = odb[h * 32 + lane];
    const float bl = rpeb[h * 32 + lane];
    const float* base = g_qT + (size_t)bh * NS * HD;

    const int s0 = blockIdx.x * 64 + wid * 8;
    const int z = s0 >> 10, y = (s0 >> 5) & 31, xb = s0 & 31;

    float at[8], al[8];
#pragma unroll
    for (int p = 0; p < 8; p++) { at[p] = bt; al[p] = bl; }

#pragma unroll
    for (int kd = 0; kd < 3; kd++) {
        int zz = z + kd - 1;
        if ((unsigned)zz >= (unsigned)Dz) continue;
#pragma unroll
        for (int kh = 0; kh < 3; kh++) {
            int yy = y + kh - 1;
            if ((unsigned)yy >= (unsigned)Hy) continue;
            const float* rowp = base + (size_t)(zz * 1024 + yy * 32) * 32 + lane;
            float w[10];
#pragma unroll
            for (int i = 0; i < 10; i++) {
                int xx = xb - 1 + i;
                w[i] = ((unsigned)xx < (unsigned)Wx) ? rowp[xx * 32] : 0.f;
            }
            const int t0 = (kd * 3 + kh) * 3;
            const float wt0 = sWt[t0][lane], wt1 = sWt[t0 + 1][lane], wt2 = sWt[t0 + 2][lane];
            const float wl0 = sWl[t0][lane], wl1 = sWl[t0 + 1][lane], wl2 = sWl[t0 + 2][lane];
#pragma unroll
            for (int p = 0; p < 8; p++) {
                at[p] += w[p] * wt0 + w[p + 1] * wt1 + w[p + 2] * wt2;
                al[p] += w[p] * wl0 + w[p + 1] * wl1 + w[p + 2] * wl2;
            }
        }
    }
#pragma unroll
    for (int p = 0; p < 8; p++) {
        size_t oi = ((size_t)bh * NS + s0 + p) * 32 + lane;
        g_tT[oi] = at[p];
        g_lepeT[oi] = al[p];
    }
}

// ================= LN + GELU + offset conv + tanh*scale =================
__global__ void k_offsets(const float* __restrict__ lnw, const float* __restrict__ lnb,
                          const float* __restrict__ opw, const float* __restrict__ opb,
                          float* __restrict__ d_out)
{
    __shared__ float sOp[18 * 192];
    __shared__ float sLn[2][192];
    for (int i = threadIdx.x; i < 18 * 192; i += 256) sOp[i] = opw[i];
    for (int i = threadIdx.x; i < 192; i += 256) { sLn[0][i] = lnw[i]; sLn[1][i] = lnb[i]; }
    __syncthreads();

    const int lane = threadIdx.x & 31, wid = threadIdx.x >> 5;
    const int gid = blockIdx.x * 8 + wid;
    const int b = gid >> 14;
    const int s = gid & (NS - 1);

    float v[6];
#pragma unroll
    for (int h = 0; h < 6; h++) v[h] = g_tT[(((size_t)b * 6 + h) * NS + s) * 32 + lane];

    float sm = 0.f;
#pragma unroll
    for (int h = 0; h < 6; h++) sm += v[h];
    sm = warpSum(sm);
    float mean = sm * (1.f / 192.f);
    float s2 = 0.f;
#pragma unroll
    for (int h = 0; h < 6; h++) { float d = v[h] - mean; s2 += d * d; }
    s2 = warpSum(s2);
    float inv = rsqrtf(s2 * (1.f / 192.f) + 1e-5f);

    float g[6];
#pragma unroll
    for (int h = 0; h < 6; h++) {
        int c = h * 32 + lane;
        float n = (v[h] - mean) * inv * sLn[0][c] + sLn[1][c];
        g[h] = 0.5f * n * (1.f + erff(n * 0.70710678118654752f));
    }

    float p18[18];
#pragma unroll
    for (int o = 0; o < 18; o++) {
        float p = 0.f;
#pragma unroll
        for (int h = 0; h < 6; h++) p += g[h] * sOp[o * 192 + h * 32 + lane];
        p18[o] = p;
    }
#pragma unroll
    for (int o = 16; o; o >>= 1)
#pragma unroll
        for (int j = 0; j < 18; j++) p18[j] += __shfl_xor_sync(0xffffffffu, p18[j], o);

    float mine = 0.f;
#pragma unroll
    for (int j = 0; j < 18; j++) if (lane == j) mine = p18[j];

    float ov = 0.f;
    if (lane < 18) {
        float val = tanhf(mine + opb[lane]);
        int comp = lane % 3;
        float sc = (comp == 2) ? (2.f / 15.f) : (2.f / 31.f);
        ov = val * sc;
        int h = lane / 3;
        size_t oi = (((size_t)b * 6 + h) * NS + s) * 3 + comp;
        g_offs[oi] = ov;
        d_out[O_OFFS + oi] = ov;
    }
    float ox = __shfl_sync(0xffffffffu, ov, (lane < 6) ? 3 * lane : 0);
    float oy = __shfl_sync(0xffffffffu, ov, (lane < 6) ? 3 * lane + 1 : 0);
    float oz = __shfl_sync(0xffffffffu, ov, (lane < 6) ? 3 * lane + 2 : 0);
    if (lane < 6) atomicAdd(&g_mag[b * 6 + lane], sqrtf(ox * ox + oy * oy + oz * oz));
}

// ================= attention epilogue (8 warps) =================
__device__ __forceinline__ void attn_epilogue(float res, int b, int h, int bi,
                                              int lane, int wid, int s0b, size_t qi)
{
    float outv = res + g_lepeT[qi];
    __shared__ float sT[8][33];
    __shared__ float sE[8];
    sT[wid][lane] = outv;
    float e = warpSum(fabsf(res));
    if (lane == 0) sE[wid] = e;
    __syncthreads();
    int ch = threadIdx.x >> 3, si = threadIdx.x & 7;
    g_attnC[((size_t)b * CH + h * 32 + ch) * NS + s0b + si] = sT[si][ch];
    if (threadIdx.x == 0) {
        float t = 0.f;
#pragma unroll
        for (int i = 0; i < 8; i++) t += sE[i];
        atomicAdd(&g_energy[b * 2 + bi], t);
    }
}

// ================= shared softmax tail over 27 (sc partials, val.y payload) =========
__device__ __forceinline__ float softmax27(float* sc, const float2* zacc, const float* bias)
{
#pragma unroll
    for (int o = 16; o; o >>= 1)
#pragma unroll
        for (int j = 0; j < 27; j++) sc[j] += __shfl_xor_sync(0xffffffffu, sc[j], o);
    float m = -1e30f;
#pragma unroll
    for (int j = 0; j < 27; j++) { sc[j] = sc[j] * SCALE + bias[j]; m = fmaxf(m, sc[j]); }
    float l = 0.f, acc = 0.f;
#pragma unroll
    for (int j = 0; j < 27; j++) {
        float p = __expf(sc[j] - m);
        l += p;
        acc += p * zacc[j].y;
    }
    return acc / l;
}

// ================= attention branch 0 (dil=1): shared 4x4x4 lattice =================
__global__ __launch_bounds__(256) void k_attn1(const float* __restrict__ bias0)
{
    const int bhh = blockIdx.y;
    const int b = bhh / 3, hh = bhh % 3;
    const int h = hh;
    const int bh = b * NH + h;
    const float* bias = bias0 + hh * 27;

    const int lane = threadIdx.x & 31, wid = threadIdx.x >> 5;
    const int s0b = blockIdx.x * 8;
    const int s = s0b + wid;
    const int z = s >> 10, y = (s >> 5) & 31, x = s & 31;

    const size_t qi = ((size_t)bh * NS + s) * 32 + lane;
    const float q = g_qT[qi];
    const float* ob = g_offs + ((size_t)bh * NS + s) * 3;
    const float bx = (float)x + ob[0] * 15.5f;
    const float by = (float)y + ob[1] * 15.5f;
    const float bz = (float)z + ob[2] * 7.5f;

    const __half2* __restrict__ kv = g_kvh + (size_t)bh * NS * HD;

    float fx = floorf(bx), fy = floorf(by), fz = floorf(bz);
    int X0 = (int)fx, Y0 = (int)fy, Z0 = (int)fz;
    float wx = bx - fx, wy = by - fy, wz = bz - fz;
    float uz = 1.f - wz;

    int LXo[4], LYo[4], LZo[4];
#pragma unroll
    for (int t = 0; t < 4; t++) {
        LXo[t] = min(max(X0 - 1 + t, 0), 31) * 32 + lane;
        LYo[t] = min(max(Y0 - 1 + t, 0), 31) * 1024;
        LZo[t] = min(max(Z0 - 1 + t, 0), 15) * 32768;
    }

    float2 zacc[27];
#pragma unroll
    for (int j = 0; j < 27; j++) zacc[j] = make_float2(0.f, 0.f);

#pragma unroll
    for (int tz = 0; tz < 4; tz++) {
        float2 P[4][4];
#pragma unroll
        for (int ty = 0; ty < 4; ty++)
#pragma unroll
            for (int tx = 0; tx < 4; tx++)
                P[ty][tx] = __half22float2(kv[LZo[tz] + LYo[ty] + LXo[tx]]);
        float2 A[4][3];
#pragma unroll
        for (int ty = 0; ty < 4; ty++)
#pragma unroll
            for (int jx = 0; jx < 3; jx++) {
                A[ty][jx].x = P[ty][jx].x + wx * (P[ty][jx + 1].x - P[ty][jx].x);
                A[ty][jx].y = P[ty][jx].y + wx * (P[ty][jx + 1].y - P[ty][jx].y);
            }
        float2 Bv[3][3];
#pragma unroll
        for (int jy = 0; jy < 3; jy++)
#pragma unroll
            for (int jx = 0; jx < 3; jx++) {
                Bv[jy][jx].x = A[jy][jx].x + wy * (A[jy + 1][jx].x - A[jy][jx].x);
                Bv[jy][jx].y = A[jy][jx].y + wy * (A[jy + 1][jx].y - A[jy][jx].y);
            }
        if (tz < 3) {
#pragma unroll
            for (int r = 0; r < 9; r++) {
                zacc[tz * 9 + r].x += uz * Bv[r / 3][r % 3].x;
                zacc[tz * 9 + r].y += uz * Bv[r / 3][r % 3].y;
            }
        }
        if (tz > 0) {
#pragma unroll
            for (int r = 0; r < 9; r++) {
                zacc[(tz - 1) * 9 + r].x += wz * Bv[r / 3][r % 3].x;
                zacc[(tz - 1) * 9 + r].y += wz * Bv[r / 3][r % 3].y;
            }
        }
    }

    float sc[27];
#pragma unroll
    for (int j = 0; j < 27; j++) sc[j] = q * zacc[j].x;
    float res = softmax27(sc, zacc, bias);
    attn_epilogue(res, b, h, 0, lane, wid, s0b, qi);
}

// ============ attention branch 1 (dil=2): separable disjoint 6x6x6 lattice ============
__global__ __launch_bounds__(256) void k_attn2(const float* __restrict__ bias1)
{
    const int bhh = blockIdx.y;
    const int b = bhh / 3, hh = bhh % 3;
    const int h = hh + 3;
    const int bh = b * NH + h;
    const float* bias = bias1 + hh * 27;

    const int lane = threadIdx.x & 31, wid = threadIdx.x >> 5;
    const int s0b = blockIdx.x * 8;
    const int s = s0b + wid;
    const int z = s >> 10, y = (s >> 5) & 31, x = s & 31;

    const size_t qi = ((size_t)bh * NS + s) * 32 + lane;
    const float q = g_qT[qi];
    const float* ob = g_offs + ((size_t)bh * NS + s) * 3;
    const float bx = (float)x + ob[0] * 15.5f;
    const float by = (float)y + ob[1] * 15.5f;
    const float bz = (float)z + ob[2] * 7.5f;

    const __half2* __restrict__ kv = g_kvh + (size_t)bh * NS * HD;

    float fx = floorf(bx), fy = floorf(by), fz = floorf(bz);
    int X0 = (int)fx, Y0 = (int)fy, Z0 = (int)fz;
    float wx = bx - fx, wy = by - fy, wz = bz - fz;
    float uz = 1.f - wz;

    int LXo[6], LYo[6], LZo[6];
#pragma unroll
    for (int t = 0; t < 6; t++) {
        LXo[t] = min(max(X0 - 2 + t, 0), 31) * 32 + lane;
        LYo[t] = min(max(Y0 - 2 + t, 0), 31) * 1024;
        LZo[t] = min(max(Z0 - 2 + t, 0), 15) * 32768;
    }

    float2 zacc[27];
#pragma unroll
    for (int j = 0; j < 27; j++) zacc[j] = make_float2(0.f, 0.f);

#pragma unroll
    for (int tz = 0; tz < 6; tz++) {
        float2 A[6][3];
#pragma unroll
        for (int ty = 0; ty < 6; ty++)
#pragma unroll
            for (int jx = 0; jx < 3; jx++) {
                float2 a = __half22float2(kv[LZo[tz] + LYo[ty] + LXo[2 * jx]]);
                float2 c = __half22float2(kv[LZo[tz] + LYo[ty] + LXo[2 * jx + 1]]);
                A[ty][jx].x = a.x + wx * (c.x - a.x);
                A[ty][jx].y = a.y + wx * (c.y - a.y);
            }
        float2 Bv[3][3];
#pragma unroll
        for (int jy = 0; jy < 3; jy++)
#pragma unroll
            for (int jx = 0; jx < 3; jx++) {
                Bv[jy][jx].x = A[2 * jy][jx].x + wy * (A[2 * jy + 1][jx].x - A[2 * jy][jx].x);
                Bv[jy][jx].y = A[2 * jy][jx].y + wy * (A[2 * jy + 1][jx].y - A[2 * jy][jx].y);
            }
        const int jz = tz >> 1;
        const float wzz = (tz & 1) ? wz : uz;
#pragma unroll
        for (int r = 0; r < 9; r++) {
            zacc[jz * 9 + r].x += wzz * Bv[r / 3][r % 3].x;
            zacc[jz * 9 + r].y += wzz * Bv[r / 3][r % 3].y;
        }
    }

    float sc[27];
#pragma unroll
    for (int j = 0; j < 27; j++) sc[j] = q * zacc[j].x;
    float res = softmax27(sc, zacc, bias);
    attn_epilogue(res, b, h, 1, lane, wid, s0b, qi);
}

// ================= final conv: g_attnC [b,c,s] x pw -> out [b,c,s]  (64x64) ==========
__global__ __launch_bounds__(256) void k_gemm_final(const float* __restrict__ W,
                                                    const float* __restrict__ bias,
                                                    float* __restrict__ out)
{
    const int b  = blockIdx.z;
    const int o0 = blockIdx.y * 64;
    const int s0 = blockIdx.x * 64;
    const int tid = threadIdx.x;
    const int tx = tid & 15, ty = tid >> 4;

    __shared__ __align__(16) float sW[16][68];
    __shared__ __align__(16) float sX[16][68];

    float acc[4][4] = {};
    const float* Xb = g_attnC + (size_t)b * CH * NS;

    for (int kk = 0; kk < CH; kk += 16) {
        {
            int r = tid >> 2, cq = (tid & 3) * 4;
            float4 w4 = *(const float4*)&W[(o0 + r) * CH + kk + cq];
            sW[cq + 0][r] = w4.x; sW[cq + 1][r] = w4.y;
            sW[cq + 2][r] = w4.z; sW[cq + 3][r] = w4.w;
        }
        {
            int r = tid >> 4, cq = (tid & 15) * 4;
            *(float4*)&sX[r][cq] = *(const float4*)&Xb[(size_t)(kk + r) * NS + s0 + cq];
        }
        __syncthreads();
#pragma unroll
        for (int k = 0; k < 16; k++) {
            float4 av = *(const float4*)&sW[k][ty * 4];
            float4 bv = *(const float4*)&sX[k][tx * 4];
            acc[0][0] += av.x*bv.x; acc[0][1] += av.x*bv.y; acc[0][2] += av.x*bv.z; acc[0][3] += av.x*bv.w;
            acc[1][0] += av.y*bv.x; acc[1][1] += av.y*bv.y; acc[1][2] += av.y*bv.z; acc[1][3] += av.y*bv.w;
            acc[2][0] += av.z*bv.x; acc[2][1] += av.z*bv.y; acc[2][2] += av.z*bv.z; acc[2][3] += av.z*bv.w;
            acc[3][0] += av.w*bv.x; acc[3][1] += av.w*bv.y; acc[3][2] += av.w*bv.z; acc[3][3] += av.w*bv.w;
        }
        __syncthreads();
    }
#pragma unroll
    for (int i = 0; i < 4; i++) {
        int o = o0 + ty * 4 + i;
        float bv = bias[o];
        float4 r = make_float4(acc[i][0] + bv, acc[i][1] + bv, acc[i][2] + bv, acc[i][3] + bv);
        *(float4*)&out[O_OUT + ((size_t)b * CH + o) * NS + s0 + tx * 4] = r;
    }
}

__global__ void k_finalize(float* __restrict__ out)
{
    int t = threadIdx.x;
    const float inv_sp = 1.f / (float)NS;
    const float inv_en = 1.f / (3.f * 32.f * (float)NS);
    if (t < 12) out[O_MAG + t] = g_mag[t] * inv_sp;
    if (t < 4)  out[O_EN + t] = g_energy[t] * inv_en;
    if (t < 16) {
        int b = t >> 3, j = t & 7;
        out[O_GUIDE + t] = (j < 6) ? g_mag[b * 6 + j] * inv_sp
                                   : g_energy[b * 2 + (j - 6)] * inv_en;
    }
}

extern "C" void kernel_launch(void* const* d_in, const int* in_sizes, int n_in,
                              void* d_out, int out_size)
{
    const float* x    = (const float*)d_in[0];
    const float* qw   = (const float*)d_in[1];
    const float* qb   = (const float*)d_in[2];
    const float* kw   = (const float*)d_in[3];
    const float* kbi  = (const float*)d_in[4];
    const float* vw   = (const float*)d_in[5];
    const float* vbi  = (const float*)d_in[6];
    const float* pw   = (const float*)d_in[7];
    const float* pb   = (const float*)d_in[8];
    const float* odw  = (const float*)d_in[9];
    const float* odb  = (const float*)d_in[10];
    const float* lnw  = (const float*)d_in[11];
    const float* lnb  = (const float*)d_in[12];
    const float* opw  = (const float*)d_in[13];
    const float* opb  = (const float*)d_in[14];
    const float* rpew = (const float*)d_in[15];
    const float* rpeb = (const float*)d_in[16];
    const float* b0   = (const float*)d_in[17];
    const float* b1   = (const float*)d_in[18];
    float* out = (float*)d_out;

    k_zero<<<1, 32>>>();

    dim3 gG(NS / 64, CH / 64, Bc);
    k_gemm_qkv<<<gG, 256>>>(x, qw, qb, kw, kbi, vw, vbi);

    k_dwconv<<<dim3(NS / 64, Bc * NH), 256>>>(odw, odb, rpew, rpeb);
    k_offsets<<<dim3(Bc * NS / 8), 256>>>(lnw, lnb, opw, opb, out);

    k_attn1<<<dim3(NS / 8, Bc * 3), 256>>>(b0);
    k_attn2<<<dim3(NS / 8, Bc * 3), 256>>>(b1);

    k_gemm_final<<<gG, 256>>>(pw, pb, out);
    k_finalize<<<1, 32>>>(out);
}

// round 17
// speedup vs baseline: 1.3577x; 1.0072x over previous
#include <cuda_runtime.h>
#include <cuda_bf16.h>
#include <cuda_fp16.h>
#include <math.h>

#define Bc 2
#define NH 6
#define HD 32
#define Dz 16
#define Hy 32
#define Wx 32
#define NS (Dz*Hy*Wx)      // 16384
#define CH 192
#define SCALE 0.17677669529663687f

// Output regions (tuple concat): out, offs, offset_mag, branch_energy, guide
#define O_OUT   0
#define O_OFFS  6291456     // 2*192*16384
#define O_MAG   6881280     // + 2*6*16384*3
#define O_EN    6881292
#define O_GUIDE 6881296

// Scratch (device globals; allocation-free)
__device__ float   g_qT[Bc*NH*NS*HD];      // [bh][s][hd]
__device__ __half2 g_kvh[Bc*NH*NS*HD];     // [bh][s][hd] -> (k, v) fp16
__device__ float   g_tT[Bc*NH*NS*HD];
__device__ float   g_lepeT[Bc*NH*NS*HD];
__device__ float   g_attnC[Bc*CH*NS];      // [b][c][s]  (attn + lepe)
__device__ float   g_offs[Bc*NH*NS*3];
__device__ float   g_mag[Bc*NH];
__device__ float   g_energy[Bc*2];

__device__ __forceinline__ float warpSum(float v) {
#pragma unroll
    for (int o = 16; o; o >>= 1) v += __shfl_xor_sync(0xffffffffu, v, o);
    return v;
}

// ========== FUSED GEMM: q, k, v conv in one pass over X (64x64 tiles) ==========
// Block (0,0,0) also zeroes the small accumulators (replaces k_zero launch).
__global__ __launch_bounds__(256) void k_gemm_qkv(const float* __restrict__ X,
                                                  const float* __restrict__ Wq, const float* __restrict__ bq,
                                                  const float* __restrict__ Wk, const float* __restrict__ bk,
                                                  const float* __restrict__ Wv, const float* __restrict__ bv_)
{
    if (blockIdx.x == 0 && blockIdx.y == 0 && blockIdx.z == 0) {
        int t = threadIdx.x;
        if (t < Bc*NH) g_mag[t] = 0.f;
        if (t < Bc*2)  g_energy[t] = 0.f;
    }

    const int b  = blockIdx.z;
    const int o0 = blockIdx.y * 64;
    const int s0 = blockIdx.x * 64;
    const int tid = threadIdx.x;
    const int tx = tid & 15, ty = tid >> 4;

    __shared__ __align__(16) float sWq[16][68];
    __shared__ __align__(16) float sWk[16][68];
    __shared__ __align__(16) float sWv[16][68];
    __shared__ __align__(16) float sX[16][68];
    __shared__ __align__(16) float sC[64][65];     // staging: first q (float), then kv (half2)

    float aq[4][4] = {}, ak[4][4] = {}, av_[4][4] = {};
    const float* Xb = X + (size_t)b * CH * NS;

    for (int kk = 0; kk < CH; kk += 16) {
        {
            int r = tid >> 2, cq = (tid & 3) * 4;
            float4 wq4 = *(const float4*)&Wq[(o0 + r) * CH + kk + cq];
            sWq[cq + 0][r] = wq4.x; sWq[cq + 1][r] = wq4.y; sWq[cq + 2][r] = wq4.z; sWq[cq + 3][r] = wq4.w;
            float4 wk4 = *(const float4*)&Wk[(o0 + r) * CH + kk + cq];
            sWk[cq + 0][r] = wk4.x; sWk[cq + 1][r] = wk4.y; sWk[cq + 2][r] = wk4.z; sWk[cq + 3][r] = wk4.w;
            float4 wv4 = *(const float4*)&Wv[(o0 + r) * CH + kk + cq];
            sWv[cq + 0][r] = wv4.x; sWv[cq + 1][r] = wv4.y; sWv[cq + 2][r] = wv4.z; sWv[cq + 3][r] = wv4.w;
        }
        {
            int r = tid >> 4, cq = (tid & 15) * 4;
            *(float4*)&sX[r][cq] = *(const float4*)&Xb[(size_t)(kk + r) * NS + s0 + cq];
        }
        __syncthreads();
#pragma unroll
        for (int k = 0; k < 16; k++) {
            float4 wq = *(const float4*)&sWq[k][ty * 4];
            float4 wk = *(const float4*)&sWk[k][ty * 4];
            float4 wv = *(const float4*)&sWv[k][ty * 4];
            float4 xv = *(const float4*)&sX[k][tx * 4];
            float wqv[4] = {wq.x, wq.y, wq.z, wq.w};
            float wkv[4] = {wk.x, wk.y, wk.z, wk.w};
            float wvv[4] = {wv.x, wv.y, wv.z, wv.w};
            float xvv[4] = {xv.x, xv.y, xv.z, xv.w};
#pragma unroll
            for (int i = 0; i < 4; i++)
#pragma unroll
                for (int j = 0; j < 4; j++) {
                    aq[i][j]  += wqv[i] * xvv[j];
                    ak[i][j]  += wkv[i] * xvv[j];
                    av_[i][j] += wvv[i] * xvv[j];
                }
        }
        __syncthreads();
    }

    // ---- stage + write q ----
#pragma unroll
    for (int i = 0; i < 4; i++) {
        float bv = bq[o0 + ty * 4 + i];
#pragma unroll
        for (int j = 0; j < 4; j++) sC[ty * 4 + i][tx * 4 + j] = aq[i][j] + bv;
    }
    __syncthreads();
#pragma unroll
    for (int it = 0; it < 16; ++it) {
        int idx = tid + it * 256;
        int sl = idx >> 6, ol = idx & 63;
        int o = o0 + ol;
        g_qT[(((size_t)b * NH + (o >> 5)) * NS + (s0 + sl)) * HD + (o & 31)] = sC[ol][sl];
    }
    __syncthreads();

    // ---- stage + write kv (reuse sC as half2) ----
    __half2 (*sC2)[65] = reinterpret_cast<__half2(*)[65]>(sC);
#pragma unroll
    for (int i = 0; i < 4; i++) {
        int o = o0 + ty * 4 + i;
        float bkk = bk[o], bvv = bv_[o];
#pragma unroll
        for (int j = 0; j < 4; j++)
            sC2[ty * 4 + i][tx * 4 + j] = __floats2half2_rn(ak[i][j] + bkk, av_[i][j] + bvv);
    }
    __syncthreads();
#pragma unroll
    for (int it = 0; it < 16; ++it) {
        int idx = tid + it * 256;
        int sl = idx >> 6, ol = idx & 63;
        int o = o0 + ol;
        g_kvh[(((size_t)b * NH + (o >> 5)) * NS + (s0 + sl)) * HD + (o & 31)] = sC2[ol][sl];
    }
}

// ================= depthwise 3x3x3 on qT -> tT & lepeT (x-register-blocked) =================
__global__ __launch_bounds__(256) void k_dwconv(const float* __restrict__ odw, const float* __restrict__ odb,
                                                const float* __restrict__ rpew, const float* __restrict__ rpeb)
{
    const int bh = blockIdx.y;
    const int h = bh % NH;
    const int lane = threadIdx.x & 31, wid = threadIdx.x >> 5;

    __shared__ float sWt[27][32];
    __shared__ float sWl[27][32];
    for (int idx = threadIdx.x; idx < 27 * 32; idx += 256) {
        int c = idx & 31, tap = idx >> 5;
        sWt[tap][c] = odw[(h * 32 + c) * 27 + tap];
        sWl[tap][c] = rpew[(h * 32 + c) * 27 + tap];
    }
    __syncthreads();

    const float bt = odb[h * 32 + lane];
    const float bl = rpeb[h * 32 + lane];
    const float* base = g_qT + (size_t)bh * NS * HD;

    const int s0 = blockIdx.x * 64 + wid * 8;
    const int z = s0 >> 10, y = (s0 >> 5) & 31, xb = s0 & 31;

    float at[8], al[8];
#pragma unroll
    for (int p = 0; p < 8; p++) { at[p] = bt; al[p] = bl; }

#pragma unroll
    for (int kd = 0; kd < 3; kd++) {
        int zz = z + kd - 1;
        if ((unsigned)zz >= (unsigned)Dz) continue;
#pragma unroll
        for (int kh = 0; kh < 3; kh++) {
            int yy = y + kh - 1;
            if ((unsigned)yy >= (unsigned)Hy) continue;
            const float* rowp = base + (size_t)(zz * 1024 + yy * 32) * 32 + lane;
            float w[10];
#pragma unroll
            for (int i = 0; i < 10; i++) {
                int xx = xb - 1 + i;
                w[i] = ((unsigned)xx < (unsigned)Wx) ? rowp[xx * 32] : 0.f;
            }
            const int t0 = (kd * 3 + kh) * 3;
            const float wt0 = sWt[t0][lane], wt1 = sWt[t0 + 1][lane], wt2 = sWt[t0 + 2][lane];
            const float wl0 = sWl[t0][lane], wl1 = sWl[t0 + 1][lane], wl2 = sWl[t0 + 2][lane];
#pragma unroll
            for (int p = 0; p < 8; p++) {
                at[p] += w[p] * wt0 + w[p + 1] * wt1 + w[p + 2] * wt2;
                al[p] += w[p] * wl0 + w[p + 1] * wl1 + w[p + 2] * wl2;
            }
        }
    }
#pragma unroll
    for (int p = 0; p < 8; p++) {
        size_t oi = ((size_t)bh * NS + s0 + p) * 32 + lane;
        g_tT[oi] = at[p];
        g_lepeT[oi] = al[p];
    }
}

// ================= LN + GELU + offset conv + tanh*scale =================
__global__ void k_offsets(const float* __restrict__ lnw, const float* __restrict__ lnb,
                          const float* __restrict__ opw, const float* __restrict__ opb,
                          float* __restrict__ d_out)
{
    __shared__ float2 sOp[18][3][32];      // [o][h-pair][lane]
    __shared__ float sLn[2][192];
    __shared__ float sMag[6];
    for (int idx = threadIdx.x; idx < 18 * 3 * 32; idx += 256) {
        int o = idx / 96, r = idx % 96;
        int p = r >> 5, lane = r & 31;
        sOp[o][p][lane] = make_float2(opw[o * 192 + (2 * p) * 32 + lane],
                                      opw[o * 192 + (2 * p + 1) * 32 + lane]);
    }
    for (int i = threadIdx.x; i < 192; i += 256) { sLn[0][i] = lnw[i]; sLn[1][i] = lnb[i]; }
    if (threadIdx.x < 6) sMag[threadIdx.x] = 0.f;
    __syncthreads();

    const int lane = threadIdx.x & 31, wid = threadIdx.x >> 5;
    const int gid = blockIdx.x * 8 + wid;
    const int b = gid >> 14;
    const int s = gid & (NS - 1);

    float v[6];
#pragma unroll
    for (int h = 0; h < 6; h++) v[h] = g_tT[(((size_t)b * 6 + h) * NS + s) * 32 + lane];

    float sm = 0.f;
#pragma unroll
    for (int h = 0; h < 6; h++) sm += v[h];
    sm = warpSum(sm);
    float mean = sm * (1.f / 192.f);
    float s2 = 0.f;
#pragma unroll
    for (int h = 0; h < 6; h++) { float d = v[h] - mean; s2 += d * d; }
    s2 = warpSum(s2);
    float inv = rsqrtf(s2 * (1.f / 192.f) + 1e-5f);

    float g[6];
#pragma unroll
    for (int h = 0; h < 6; h++) {
        int c = h * 32 + lane;
        float n = (v[h] - mean) * inv * sLn[0][c] + sLn[1][c];
        g[h] = 0.5f * n * (1.f + erff(n * 0.70710678118654752f));
    }

    float p18[18];
#pragma unroll
    for (int o = 0; o < 18; o++) {
        float2 w0 = sOp[o][0][lane];
        float2 w1 = sOp[o][1][lane];
        float2 w2 = sOp[o][2][lane];
        p18[o] = g[0] * w0.x + g[1] * w0.y + g[2] * w1.x + g[3] * w1.y + g[4] * w2.x + g[5] * w2.y;
    }
#pragma unroll
    for (int o = 16; o; o >>= 1)
#pragma unroll
        for (int j = 0; j < 18; j++) p18[j] += __shfl_xor_sync(0xffffffffu, p18[j], o);

    float mine = 0.f;
#pragma unroll
    for (int j = 0; j < 18; j++) if (lane == j) mine = p18[j];

    float ov = 0.f;
    if (lane < 18) {
        float val = tanhf(mine + opb[lane]);
        int comp = lane % 3;
        float sc = (comp == 2) ? (2.f / 15.f) : (2.f / 31.f);
        ov = val * sc;
        int h = lane / 3;
        size_t oi = (((size_t)b * 6 + h) * NS + s) * 3 + comp;
        g_offs[oi] = ov;
        d_out[O_OFFS + oi] = ov;
    }
    // per-head offset magnitude: aggregate in smem, one global atomic set per block
    float ox = __shfl_sync(0xffffffffu, ov, (lane < 6) ? 3 * lane : 0);
    float oy = __shfl_sync(0xffffffffu, ov, (lane < 6) ? 3 * lane + 1 : 0);
    float oz = __shfl_sync(0xffffffffu, ov, (lane < 6) ? 3 * lane + 2 : 0);
    if (lane < 6) atomicAdd(&sMag[lane], sqrtf(ox * ox + oy * oy + oz * oz));
    __syncthreads();
    if (threadIdx.x < 6) atomicAdd(&g_mag[b * 6 + threadIdx.x], sMag[threadIdx.x]);
}

// ================= attention epilogue (8 warps) =================
__device__ __forceinline__ void attn_epilogue(float res, int b, int h, int bi,
                                              int lane, int wid, int s0b, size_t qi)
{
    float outv = res + g_lepeT[qi];
    __shared__ float sT[8][33];
    __shared__ float sE[8];
    sT[wid][lane] = outv;
    float e = warpSum(fabsf(res));
    if (lane == 0) sE[wid] = e;
    __syncthreads();
    int ch = threadIdx.x >> 3, si = threadIdx.x & 7;
    g_attnC[((size_t)b * CH + h * 32 + ch) * NS + s0b + si] = sT[si][ch];
    if (threadIdx.x == 0) {
        float t = 0.f;
#pragma unroll
        for (int i = 0; i < 8; i++) t += sE[i];
        atomicAdd(&g_energy[b * 2 + bi], t);
    }
}

// ================= shared softmax tail over 27 (sc partials, val.y payload) =========
__device__ __forceinline__ float softmax27(float* sc, const float2* zacc, const float* bias)
{
#pragma unroll
    for (int o = 16; o; o >>= 1)
#pragma unroll
        for (int j = 0; j < 27; j++) sc[j] += __shfl_xor_sync(0xffffffffu, sc[j], o);
    float m = -1e30f;
#pragma unroll
    for (int j = 0; j < 27; j++) { sc[j] = sc[j] * SCALE + bias[j]; m = fmaxf(m, sc[j]); }
    float l = 0.f, acc = 0.f;
#pragma unroll
    for (int j = 0; j < 27; j++) {
        float p = __expf(sc[j] - m);
        l += p;
        acc += p * zacc[j].y;
    }
    return acc / l;
}

// ================= attention branch 0 (dil=1): shared 4x4x4 lattice =================
__global__ __launch_bounds__(256) void k_attn1(const float* __restrict__ bias0)
{
    const int bhh = blockIdx.y;
    const int b = bhh / 3, hh = bhh % 3;
    const int h = hh;
    const int bh = b * NH + h;
    const float* bias = bias0 + hh * 27;

    const int lane = threadIdx.x & 31, wid = threadIdx.x >> 5;
    const int s0b = blockIdx.x * 8;
    const int s = s0b + wid;
    const int z = s >> 10, y = (s >> 5) & 31, x = s & 31;

    const size_t qi = ((size_t)bh * NS + s) * 32 + lane;
    const float q = g_qT[qi];
    const float* ob = g_offs + ((size_t)bh * NS + s) * 3;
    const float bx = (float)x + ob[0] * 15.5f;
    const float by = (float)y + ob[1] * 15.5f;
    const float bz = (float)z + ob[2] * 7.5f;

    const __half2* __restrict__ kv = g_kvh + (size_t)bh * NS * HD;

    float fx = floorf(bx), fy = floorf(by), fz = floorf(bz);
    int X0 = (int)fx, Y0 = (int)fy, Z0 = (int)fz;
    float wx = bx - fx, wy = by - fy, wz = bz - fz;
    float uz = 1.f - wz;

    int LXo[4], LYo[4], LZo[4];
#pragma unroll
    for (int t = 0; t < 4; t++) {
        LXo[t] = min(max(X0 - 1 + t, 0), 31) * 32 + lane;
        LYo[t] = min(max(Y0 - 1 + t, 0), 31) * 1024;
        LZo[t] = min(max(Z0 - 1 + t, 0), 15) * 32768;
    }

    float2 zacc[27];
#pragma unroll
    for (int j = 0; j < 27; j++) zacc[j] = make_float2(0.f, 0.f);

#pragma unroll
    for (int tz = 0; tz < 4; tz++) {
        float2 P[4][4];
#pragma unroll
        for (int ty = 0; ty < 4; ty++)
#pragma unroll
            for (int tx = 0; tx < 4; tx++)
                P[ty][tx] = __half22float2(kv[LZo[tz] + LYo[ty] + LXo[tx]]);
        float2 A[4][3];
#pragma unroll
        for (int ty = 0; ty < 4; ty++)
#pragma unroll
            for (int jx = 0; jx < 3; jx++) {
                A[ty][jx].x = P[ty][jx].x + wx * (P[ty][jx + 1].x - P[ty][jx].x);
                A[ty][jx].y = P[ty][jx].y + wx * (P[ty][jx + 1].y - P[ty][jx].y);
            }
        float2 Bv[3][3];
#pragma unroll
        for (int jy = 0; jy < 3; jy++)
#pragma unroll
            for (int jx = 0; jx < 3; jx++) {
                Bv[jy][jx].x = A[jy][jx].x + wy * (A[jy + 1][jx].x - A[jy][jx].x);
                Bv[jy][jx].y = A[jy][jx].y + wy * (A[jy + 1][jx].y - A[jy][jx].y);
            }
        if (tz < 3) {
#pragma unroll
            for (int r = 0; r < 9; r++) {
                zacc[tz * 9 + r].x += uz * Bv[r / 3][r % 3].x;
                zacc[tz * 9 + r].y += uz * Bv[r / 3][r % 3].y;
            }
        }
        if (tz > 0) {
#pragma unroll
            for (int r = 0; r < 9; r++) {
                zacc[(tz - 1) * 9 + r].x += wz * Bv[r / 3][r % 3].x;
                zacc[(tz - 1) * 9 + r].y += wz * Bv[r / 3][r % 3].y;
            }
        }
    }

    float sc[27];
#pragma unroll
    for (int j = 0; j < 27; j++) sc[j] = q * zacc[j].x;
    float res = softmax27(sc, zacc, bias);
    attn_epilogue(res, b, h, 0, lane, wid, s0b, qi);
}

// ============ attention branch 1 (dil=2): separable disjoint 6x6x6 lattice ============
__global__ __launch_bounds__(256) void k_attn2(const float* __restrict__ bias1)
{
    const int bhh = blockIdx.y;
    const int b = bhh / 3, hh = bhh % 3;
    const int h = hh + 3;
    const int bh = b * NH + h;
    const float* bias = bias1 + hh * 27;

    const int lane = threadIdx.x & 31, wid = threadIdx.x >> 5;
    const int s0b = blockIdx.x * 8;
    const int s = s0b + wid;
    const int z = s >> 10, y = (s >> 5) & 31, x = s & 31;

    const size_t qi = ((size_t)bh * NS + s) * 32 + lane;
    const float q = g_qT[qi];
    const float* ob = g_offs + ((size_t)bh * NS + s) * 3;
    const float bx = (float)x + ob[0] * 15.5f;
    const float by = (float)y + ob[1] * 15.5f;
    const float bz = (float)z + ob[2] * 7.5f;

    const __half2* __restrict__ kv = g_kvh + (size_t)bh * NS * HD;

    float fx = floorf(bx), fy = floorf(by), fz = floorf(bz);
    int X0 = (int)fx, Y0 = (int)fy, Z0 = (int)fz;
    float wx = bx - fx, wy = by - fy, wz = bz - fz;
    float uz = 1.f - wz;

    int LXo[6], LYo[6], LZo[6];
#pragma unroll
    for (int t = 0; t < 6; t++) {
        LXo[t] = min(max(X0 - 2 + t, 0), 31) * 32 + lane;
        LYo[t] = min(max(Y0 - 2 + t, 0), 31) * 1024;
        LZo[t] = min(max(Z0 - 2 + t, 0), 15) * 32768;
    }

    float2 zacc[27];
#pragma unroll
    for (int j = 0; j < 27; j++) zacc[j] = make_float2(0.f, 0.f);

#pragma unroll
    for (int tz = 0; tz < 6; tz++) {
        float2 A[6][3];
#pragma unroll
        for (int ty = 0; ty < 6; ty++)
#pragma unroll
            for (int jx = 0; jx < 3; jx++) {
                float2 a = __half22float2(kv[LZo[tz] + LYo[ty] + LXo[2 * jx]]);
                float2 c = __half22float2(kv[LZo[tz] + LYo[ty] + LXo[2 * jx + 1]]);
                A[ty][jx].x = a.x + wx * (c.x - a.x);
                A[ty][jx].y = a.y + wx * (c.y - a.y);
            }
        float2 Bv[3][3];
#pragma unroll
        for (int jy = 0; jy < 3; jy++)
#pragma unroll
            for (int jx = 0; jx < 3; jx++) {
                Bv[jy][jx].x = A[2 * jy][jx].x + wy * (A[2 * jy + 1][jx].x - A[2 * jy][jx].x);
                Bv[jy][jx].y = A[2 * jy][jx].y + wy * (A[2 * jy + 1][jx].y - A[2 * jy][jx].y);
            }
        const int jz = tz >> 1;
        const float wzz = (tz & 1) ? wz : uz;
#pragma unroll
        for (int r = 0; r < 9; r++) {
            zacc[jz * 9 + r].x += wzz * Bv[r / 3][r % 3].x;
            zacc[jz * 9 + r].y += wzz * Bv[r / 3][r % 3].y;
        }
    }

    float sc[27];
#pragma unroll
    for (int j = 0; j < 27; j++) sc[j] = q * zacc[j].x;
    float res = softmax27(sc, zacc, bias);
    attn_epilogue(res, b, h, 1, lane, wid, s0b, qi);
}

// ================= final conv: g_attnC [b,c,s] x pw -> out [b,c,s]  (64x64) ==========
__global__ __launch_bounds__(256) void k_gemm_final(const float* __restrict__ W,
                                                    const float* __restrict__ bias,
                                                    float* __restrict__ out)
{
    const int b  = blockIdx.z;
    const int o0 = blockIdx.y * 64;
    const int s0 = blockIdx.x * 64;
    const int tid = threadIdx.x;
    const int tx = tid & 15, ty = tid >> 4;

    __shared__ __align__(16) float sW[16][68];
    __shared__ __align__(16) float sX[16][68];

    float acc[4][4] = {};
    const float* Xb = g_attnC + (size_t)b * CH * NS;

    for (int kk = 0; kk < CH; kk += 16) {
        {
            int r = tid >> 2, cq = (tid & 3) * 4;
            float4 w4 = *(const float4*)&W[(o0 + r) * CH + kk + cq];
            sW[cq + 0][r] = w4.x; sW[cq + 1][r] = w4.y;
            sW[cq + 2][r] = w4.z; sW[cq + 3][r] = w4.w;
        }
        {
            int r = tid >> 4, cq = (tid & 15) * 4;
            *(float4*)&sX[r][cq] = *(const float4*)&Xb[(size_t)(kk + r) * NS + s0 + cq];
        }
        __syncthreads();
#pragma unroll
        for (int k = 0; k < 16; k++) {
            float4 av = *(const float4*)&sW[k][ty * 4];
            float4 bv = *(const float4*)&sX[k][tx * 4];
            acc[0][0] += av.x*bv.x; acc[0][1] += av.x*bv.y; acc[0][2] += av.x*bv.z; acc[0][3] += av.x*bv.w;
            acc[1][0] += av.y*bv.x; acc[1][1] += av.y*bv.y; acc[1][2] += av.y*bv.z; acc[1][3] += av.y*bv.w;
            acc[2][0] += av.z*bv.x; acc[2][1] += av.z*bv.y; acc[2][2] += av.z*bv.z; acc[2][3] += av.z*bv.w;
            acc[3][0] += av.w*bv.x; acc[3][1] += av.w*bv.y; acc[3][2] += av.w*bv.z; acc[3][3] += av.w*bv.w;
        }
        __syncthreads();
    }
#pragma unroll
    for (int i = 0; i < 4; i++) {
        int o = o0 + ty * 4 + i;
        float bv = bias[o];
        float4 r = make_float4(acc[i][0] + bv, acc[i][1] + bv, acc[i][2] + bv, acc[i][3] + bv);
        *(float4*)&out[O_OUT + ((size_t)b * CH + o) * NS + s0 + tx * 4] = r;
    }
}

__global__ void k_finalize(float* __restrict__ out)
{
    int t = threadIdx.x;
    const float inv_sp = 1.f / (float)NS;
    const float inv_en = 1.f / (3.f * 32.f * (float)NS);
    if (t < 12) out[O_MAG + t] = g_mag[t] * inv_sp;
    if (t < 4)  out[O_EN + t] = g_energy[t] * inv_en;
    if (t < 16) {
        int b = t >> 3, j = t & 7;
        out[O_GUIDE + t] = (j < 6) ? g_mag[b * 6 + j] * inv_sp
                                   : g_energy[b * 2 + (j - 6)] * inv_en;
    }
}

extern "C" void kernel_launch(void* const* d_in, const int* in_sizes, int n_in,
                              void* d_out, int out_size)
{
    const float* x    = (const float*)d_in[0];
    const float* qw   = (const float*)d_in[1];
    const float* qb   = (const float*)d_in[2];
    const float* kw   = (const float*)d_in[3];
    const float* kbi  = (const float*)d_in[4];
    const float* vw   = (const float*)d_in[5];
    const float* vbi  = (const float*)d_in[6];
    const float* pw   = (const float*)d_in[7];
    const float* pb   = (const float*)d_in[8];
    const float* odw  = (const float*)d_in[9];
    const float* odb  = (const float*)d_in[10];
    const float* lnw  = (const float*)d_in[11];
    const float* lnb  = (const float*)d_in[12];
    const float* opw  = (const float*)d_in[13];
    const float* opb  = (const float*)d_in[14];
    const float* rpew = (const float*)d_in[15];
    const float* rpeb = (const float*)d_in[16];
    const float* b0   = (const float*)d_in[17];
    const float* b1   = (const float*)d_in[18];
    float* out = (float*)d_out;

    dim3 gG(NS / 64, CH / 64, Bc);
    k_gemm_qkv<<<gG, 256>>>(x, qw, qb, kw, kbi, vw, vbi);

    k_dwconv<<<dim3(NS / 64, Bc * NH), 256>>>(odw, odb, rpew, rpeb);
    k_offsets<<<dim3(Bc * NS / 8), 256>>>(lnw, lnb, opw, opb, out);

    k_attn1<<<dim3(NS / 8, Bc * 3), 256>>>(b0);
    k_attn2<<<dim3(NS / 8, Bc * 3), 256>>>(b1);

    k_gemm_final<<<gG, 256>>>(pw, pb, out);
    k_finalize<<<1, 32>>>(out);
}